// round 9
// baseline (speedup 1.0000x reference)
#include <cuda_runtime.h>
#include <cuda_bf16.h>
#include <cuda_fp16.h>
#include <math.h>
#include <stdint.h>

// ===========================================================================
// FNet block on GB300 (compute_103 PTX -> mma.sync HMMA path)
//   ft  = Re(FFT_seq(D * reverse_hidden(x)))   [FFT_D^2 = D * index reversal]
//   t   = LayerNorm(x + ft)*g + b   -> fp16
//   h   = GELU(t @ w1 + b1)         -> 1-term fp16 mma GEMM -> fp16
//   out = (h @ w2 + b2) * mask      -> 1-term fp16 mma GEMM -> fp32
// FFT: real-packed, radix-8 fused rounds (h=1,8,64) + radix-4 (h=512).
// ===========================================================================

#define B_ 8
#define S_ 2048
#define D_ 1024
#define ROWS (B_ * S_)
#define ELEMS ((long)ROWS * D_)

__device__ __align__(256) float   g_ft[ELEMS];
__device__ __align__(256) __half  g_t[ELEMS];
__device__ __align__(256) __half  g_h[ELEMS];
__device__ __align__(256) __half  g_w1h[D_ * D_];
__device__ __align__(256) __half  g_w2h[D_ * D_];
__device__ __align__(256) float2  g_tw[1024];

// ------------------------- helpers ----------------------------------------
__device__ __forceinline__ uint32_t smem_u32(const void* p) {
    uint32_t a;
    asm("{ .reg .u64 t; cvta.to.shared.u64 t, %1; cvt.u32.u64 %0, t; }"
        : "=r"(a) : "l"(p));
    return a;
}
__device__ __forceinline__ void cp16(uint32_t s, const void* g) {
    asm volatile("cp.async.cg.shared.global [%0], [%1], 16;" :: "r"(s), "l"(g));
}
#define CP_COMMIT() asm volatile("cp.async.commit_group;" ::: "memory")
#define CP_WAIT(n)  asm volatile("cp.async.wait_group %0;" :: "n"(n) : "memory")

__device__ __forceinline__ void ldsm_x4(uint32_t* r, uint32_t addr) {
    asm volatile("ldmatrix.sync.aligned.m8n8.x4.shared.b16 {%0,%1,%2,%3}, [%4];"
                 : "=r"(r[0]), "=r"(r[1]), "=r"(r[2]), "=r"(r[3]) : "r"(addr));
}
__device__ __forceinline__ void mma_f16(float* c, const uint32_t* a, const uint32_t* b) {
    asm volatile("mma.sync.aligned.m16n8k16.row.col.f32.f16.f16.f32 "
                 "{%0,%1,%2,%3}, {%4,%5,%6,%7}, {%8,%9}, {%0,%1,%2,%3};"
                 : "+f"(c[0]), "+f"(c[1]), "+f"(c[2]), "+f"(c[3])
                 : "r"(a[0]), "r"(a[1]), "r"(a[2]), "r"(a[3]),
                   "r"(b[0]), "r"(b[1]));
}
__device__ __forceinline__ float2 cmul(float2 a, float2 b) {
    return make_float2(a.x * b.x - a.y * b.y, a.x * b.y + a.y * b.x);
}
__device__ __forceinline__ float2 cadd(float2 a, float2 b) {
    return make_float2(a.x + b.x, a.y + b.y);
}
__device__ __forceinline__ float2 csub(float2 a, float2 b) {
    return make_float2(a.x - b.x, a.y - b.y);
}

// ===========================================================================
// Kernel 0a: twiddle table  tw[t] = exp(-i*pi*t/1024)
// ===========================================================================
__global__ void twinit_kernel(float2* __restrict__ tw) {
    int t = blockIdx.x * 256 + threadIdx.x;
    float s, c;
    sincospif(-(float)t / 1024.0f, &s, &c);
    tw[t] = make_float2(c, s);
}

// ===========================================================================
// Kernel 0b: weight transpose + fp16 convert.  w[K][N] -> wt[N][K] fp16
// ===========================================================================
__global__ __launch_bounds__(256) void wsplit_kernel(
    const float* __restrict__ w, __half* __restrict__ wh)
{
    __shared__ float tile[32][33];
    const int bx = blockIdx.x * 32;
    const int by = blockIdx.y * 32;
    const int tx = threadIdx.x, ty = threadIdx.y;
    for (int i = ty; i < 32; i += 8)
        tile[i][tx] = w[(long)(by + i) * D_ + bx + tx];
    __syncthreads();
    for (int i = ty; i < 32; i += 8) {
        int n = bx + i;
        int k = by + tx;
        wh[(long)n * D_ + k] = __float2half(tile[tx][i]);
    }
}

// ===========================================================================
// Kernel 1: real-packed FFT along seq (8 real cols -> 4 complex FFTs)
// Rounds: radix-8 at h=1,8,64 (stages 1..256), radix-4 at h=512 (512,1024).
// Unpack Re, scatter reversed hidden index, scale by D.
// ===========================================================================
__global__ __launch_bounds__(512) void fftc_kernel(
    const float* __restrict__ x, float* __restrict__ ft,
    const float2* __restrict__ tw)
{
    extern __shared__ float2 sa[];   // [2048][4] complex = 64 KB
    const int c0  = blockIdx.x * 8;
    const int b   = blockIdx.y;
    const int tid = threadIdx.x;

    const float* xp = x + (long)b * S_ * D_ + c0;
    for (int r = tid; r < S_; r += 512) {
        int br = __brev(r) >> 21;
        float4 v0 = *(const float4*)(xp + (long)r * D_);
        float4 v1 = *(const float4*)(xp + (long)r * D_ + 4);
        float2* d = sa + br * 4;
        d[0] = make_float2(v0.x, v0.y);
        d[1] = make_float2(v0.z, v0.w);
        d[2] = make_float2(v1.x, v1.y);
        d[3] = make_float2(v1.z, v1.w);
    }
    __syncthreads();

    const float2 w8  = make_float2(0.70710678118654752f, -0.70710678118654752f);
    const float2 w83 = make_float2(-0.70710678118654752f, -0.70710678118654752f);

    // three radix-8 rounds: h = 1, 8, 64
    #pragma unroll
    for (int h = 1; h <= 64; h *= 8) {
        const int s1 = 1024 / h, s2 = 512 / h, s3 = 256 / h;
        #pragma unroll
        for (int t = 0; t < 2; t++) {
            int i = tid + t * 512;           // 1024 work items
            int q = i & 3;
            int g = i >> 2;                  // butterfly id 0..255
            int j = g & (h - 1);
            int i0 = ((g - j) << 3) + j;

            float2 u0 = sa[(i0        ) * 4 + q];
            float2 u1 = sa[(i0 +     h) * 4 + q];
            float2 u2 = sa[(i0 + 2 * h) * 4 + q];
            float2 u3 = sa[(i0 + 3 * h) * 4 + q];
            float2 u4 = sa[(i0 + 4 * h) * 4 + q];
            float2 u5 = sa[(i0 + 5 * h) * 4 + q];
            float2 u6 = sa[(i0 + 6 * h) * 4 + q];
            float2 u7 = sa[(i0 + 7 * h) * 4 + q];

            float2 w1 = tw[j * s1];
            float2 wA = tw[j * s2];
            float2 wB = make_float2(wA.y, -wA.x);        // -i*wA
            float2 wC = tw[j * s3];
            float2 wC1 = cmul(wC, w8);
            float2 wC2 = make_float2(wC.y, -wC.x);       // -i*wC
            float2 wC3 = cmul(wC, w83);

            // level 1 (stage h)
            float2 t1 = cmul(w1, u1), t3 = cmul(w1, u3);
            float2 t5 = cmul(w1, u5), t7 = cmul(w1, u7);
            float2 b0 = cadd(u0, t1), b1 = csub(u0, t1);
            float2 b2 = cadd(u2, t3), b3 = csub(u2, t3);
            float2 b4 = cadd(u4, t5), b5 = csub(u4, t5);
            float2 b6 = cadd(u6, t7), b7 = csub(u6, t7);
            // level 2 (stage 2h)
            float2 p2 = cmul(wA, b2), p3 = cmul(wB, b3);
            float2 p6 = cmul(wA, b6), p7 = cmul(wB, b7);
            float2 cc0 = cadd(b0, p2), cc2 = csub(b0, p2);
            float2 cc1 = cadd(b1, p3), cc3 = csub(b1, p3);
            float2 cc4 = cadd(b4, p6), cc6 = csub(b4, p6);
            float2 cc5 = cadd(b5, p7), cc7 = csub(b5, p7);
            // level 3 (stage 4h)
            float2 q4 = cmul(wC,  cc4), q5 = cmul(wC1, cc5);
            float2 q6 = cmul(wC2, cc6), q7 = cmul(wC3, cc7);
            sa[(i0        ) * 4 + q] = cadd(cc0, q4);
            sa[(i0 + 4 * h) * 4 + q] = csub(cc0, q4);
            sa[(i0 +     h) * 4 + q] = cadd(cc1, q5);
            sa[(i0 + 5 * h) * 4 + q] = csub(cc1, q5);
            sa[(i0 + 2 * h) * 4 + q] = cadd(cc2, q6);
            sa[(i0 + 6 * h) * 4 + q] = csub(cc2, q6);
            sa[(i0 + 3 * h) * 4 + q] = cadd(cc3, q7);
            sa[(i0 + 7 * h) * 4 + q] = csub(cc3, q7);
        }
        __syncthreads();
    }

    // radix-4 round: h = 512 (stages 512, 1024)
    {
        const int h = 512;
        #pragma unroll
        for (int t = 0; t < 4; t++) {
            int i = tid + t * 512;
            int q = i & 3;
            int g = i >> 2;
            int j = g & (h - 1);
            int i0 = ((g - j) << 2) + j;
            float2 u0 = sa[i0 * 4 + q];
            float2 u1 = sa[(i0 + h) * 4 + q];
            float2 u2 = sa[(i0 + 2 * h) * 4 + q];
            float2 u3 = sa[(i0 + 3 * h) * 4 + q];
            float2 w1 = tw[j * 2];
            float2 wA = tw[j];
            float2 wB = make_float2(wA.y, -wA.x);
            float2 t1 = cmul(w1, u1);
            float2 a0 = cadd(u0, t1), a1 = csub(u0, t1);
            float2 t3 = cmul(w1, u3);
            float2 a2 = cadd(u2, t3), a3 = csub(u2, t3);
            float2 t2 = cmul(wA, a2);
            float2 tB = cmul(wB, a3);
            sa[i0 * 4 + q]           = cadd(a0, t2);
            sa[(i0 + h) * 4 + q]     = cadd(a1, tB);
            sa[(i0 + 2 * h) * 4 + q] = csub(a0, t2);
            sa[(i0 + 3 * h) * 4 + q] = csub(a1, tB);
        }
        __syncthreads();
    }

    float* fp = ft + (long)b * S_ * D_;
    for (int i = tid; i < S_ * 8; i += 512) {
        int s   = i >> 3;
        int col = i & 7;
        int q   = col >> 1;
        int ns  = (S_ - s) & (S_ - 1);
        float2 zs = sa[s * 4 + q];
        float2 zn = sa[ns * 4 + q];
        float val = (col & 1) ? (zs.y + zn.y) : (zs.x + zn.x);
        val *= 512.0f;                          // D * 0.5
        int dout = (D_ - (c0 + col)) & (D_ - 1);
        fp[(long)s * D_ + dout] = val;
    }
}

// ===========================================================================
// Kernel 2: t = LN(x + ft)*g + b  -> fp16  (float4 I/O)
// ===========================================================================
__device__ __forceinline__ float block_sum_256(float val, float* sh) {
    #pragma unroll
    for (int o = 16; o > 0; o >>= 1) val += __shfl_xor_sync(0xFFFFFFFFu, val, o);
    int lane = threadIdx.x & 31, w = threadIdx.x >> 5;
    if (lane == 0) sh[w] = val;
    __syncthreads();
    if (w == 0) {
        float v = (lane < 8) ? sh[lane] : 0.0f;
        #pragma unroll
        for (int o = 4; o > 0; o >>= 1) v += __shfl_xor_sync(0xFFFFFFFFu, v, o);
        if (lane == 0) sh[0] = v;
    }
    __syncthreads();
    float r = sh[0];
    __syncthreads();
    return r;
}

__global__ __launch_bounds__(256) void add_ln_kernel(
    const float* __restrict__ x, const float* __restrict__ ft,
    const float* __restrict__ gamma, const float* __restrict__ beta,
    __half* __restrict__ t_out)
{
    __shared__ float sh[8];
    const int row = blockIdx.x;
    const int tid = threadIdx.x;
    const long base = (long)row * D_ + tid * 4;

    float4 xv = *(const float4*)(x + base);
    float4 fv = *(const float4*)(ft + base);
    float v0 = xv.x + fv.x, v1 = xv.y + fv.y, v2 = xv.z + fv.z, v3 = xv.w + fv.w;

    float mu = block_sum_256(v0 + v1 + v2 + v3, sh) * (1.0f / D_);
    float d0 = v0 - mu, d1 = v1 - mu, d2 = v2 - mu, d3 = v3 - mu;
    float var = block_sum_256(d0 * d0 + d1 * d1 + d2 * d2 + d3 * d3, sh) * (1.0f / D_);
    float rs  = rsqrtf(var + 1e-5f);

    float4 gv = *(const float4*)(gamma + tid * 4);
    float4 bv = *(const float4*)(beta + tid * 4);
    float r0 = d0 * rs * gv.x + bv.x;
    float r1 = d1 * rs * gv.y + bv.y;
    float r2 = d2 * rs * gv.z + bv.z;
    float r3 = d3 * rs * gv.w + bv.w;

    __half2 h01 = __floats2half2_rn(r0, r1);
    __half2 h23 = __floats2half2_rn(r2, r3);
    uint2 pk = make_uint2(*(uint32_t*)&h01, *(uint32_t*)&h23);
    *(uint2*)(t_out + base) = pk;
}

// ===========================================================================
// Kernel 3/4: 1-term fp16 GEMM via mma.sync. Tile 128M x 256N x 64K,
// 512 threads (16 warps: 4m x 4n, warp tile 32x64), cp.async double buffer.
// fuse 0: bias+GELU -> fp16.   fuse 1: bias, *mask -> fp32.
// ===========================================================================
#define BK 64
#define ROWB 144                       // 128B data + 16B pad
#define TILE_A_B (128 * ROWB)          // 18432
#define TILE_B_B (256 * ROWB)          // 36864
#define OFF_A 0
#define OFF_BW TILE_A_B
#define STAGE_B (TILE_A_B + TILE_B_B)       // 55296
#define GEMM_SMEM (2 * STAGE_B)             // 110592

__global__ __launch_bounds__(512) void gemm_mma_kernel(
    const __half* __restrict__ A, const __half* __restrict__ Bw,
    const float* __restrict__ bias, const float* __restrict__ mask,
    __half* __restrict__ Ch, float* __restrict__ Cf, int fuse)
{
    extern __shared__ char sm[];
    const uint32_t sb  = smem_u32(sm);
    const int tid  = threadIdx.x;
    const int wid  = tid >> 5;
    const int lane = tid & 31;
    const int bm = blockIdx.y * 128;
    const int bn = blockIdx.x * 256;
    const int warp_m = wid & 3;
    const int warp_n = wid >> 2;

    auto load_stage = [&](int stage, int k0) {
        const uint32_t st = sb + stage * STAGE_B;
        #pragma unroll
        for (int t = 0; t < 2; t++) {   // A: 1024 chunks, 2 per thread
            int idx = tid + t * 512;
            int row = idx >> 3, ch = idx & 7;
            uint32_t so = row * ROWB + ch * 16;
            long ga = (long)(bm + row) * D_ + k0 + ch * 8;
            cp16(st + OFF_A + so, A + ga);
        }
        #pragma unroll
        for (int t = 0; t < 4; t++) {   // W: 2048 chunks, 4 per thread
            int idx = tid + t * 512;
            int row = idx >> 3, ch = idx & 7;
            uint32_t so = row * ROWB + ch * 16;
            long gb = (long)(bn + row) * D_ + k0 + ch * 8;
            cp16(st + OFF_BW + so, Bw + gb);
        }
    };

    float acc[2][8][4];
    #pragma unroll
    for (int m = 0; m < 2; m++)
        #pragma unroll
        for (int n = 0; n < 8; n++)
            #pragma unroll
            for (int q = 0; q < 4; q++) acc[m][n][q] = 0.0f;

    load_stage(0, 0);
    CP_COMMIT();

    const int a_lrow = lane & 15;
    const int a_kch  = lane >> 4;
    const int b_lrow = ((lane >> 4) & 1) * 8 + (lane & 7);
    const int b_kch  = (lane >> 3) & 1;

    const int NIT = D_ / BK;   // 16
    for (int it = 0; it < NIT; it++) {
        const int s = it & 1;
        if (it + 1 < NIT) {
            load_stage(s ^ 1, (it + 1) * BK);
            CP_COMMIT();
            CP_WAIT(1);
        } else {
            CP_WAIT(0);
        }
        __syncthreads();

        const uint32_t tA  = sb + s * STAGE_B + OFF_A;
        const uint32_t tBw = sb + s * STAGE_B + OFF_BW;

        #pragma unroll
        for (int ks = 0; ks < 4; ks++) {
            const int kb = ks * 32;
            uint32_t ah[2][4];
            #pragma unroll
            for (int m = 0; m < 2; m++) {
                uint32_t off = (uint32_t)((warp_m * 32 + m * 16 + a_lrow) * ROWB
                                          + kb + a_kch * 16);
                ldsm_x4(ah[m], tA + off);
            }
            #pragma unroll
            for (int p = 0; p < 4; p++) {
                uint32_t off = (uint32_t)((warp_n * 64 + p * 16 + b_lrow) * ROWB
                                          + kb + b_kch * 16);
                uint32_t rh[4];
                ldsm_x4(rh, tBw + off);
                #pragma unroll
                for (int m = 0; m < 2; m++) {
                    mma_f16(acc[m][2 * p],     ah[m], rh);
                    mma_f16(acc[m][2 * p + 1], ah[m], rh + 2);
                }
            }
        }
        __syncthreads();
    }

    // ------------------------------ epilogue -------------------------------
    const int g  = lane >> 2;
    const int t2 = (lane & 3) * 2;
    #pragma unroll
    for (int m = 0; m < 2; m++) {
        const int row0 = bm + warp_m * 32 + m * 16 + g;
        #pragma unroll
        for (int half = 0; half < 2; half++) {
            const int row = row0 + half * 8;
            const float mk = (fuse == 1) ? mask[row] : 0.0f;
            #pragma unroll
            for (int n = 0; n < 8; n++) {
                const int col = bn + warp_n * 64 + n * 8 + t2;
                float v0 = acc[m][n][2 * half]     + bias[col];
                float v1 = acc[m][n][2 * half + 1] + bias[col + 1];
                if (fuse == 0) {
                    v0 = 0.5f * v0 * (1.0f + erff(v0 * 0.70710678118654752f));
                    v1 = 0.5f * v1 * (1.0f + erff(v1 * 0.70710678118654752f));
                    __half h0 = __float2half(v0);
                    __half h1 = __float2half(v1);
                    uint32_t hp = ((uint32_t)__half_as_ushort(h1) << 16)
                                | __half_as_ushort(h0);
                    *(uint32_t*)(Ch + (long)row * D_ + col) = hp;
                } else {
                    float2 o = make_float2(v0 * mk, v1 * mk);
                    *(float2*)(Cf + (long)row * D_ + col) = o;
                }
            }
        }
    }
}

// ===========================================================================
// Launch
// ===========================================================================
extern "C" void kernel_launch(void* const* d_in, const int* in_sizes, int n_in,
                              void* d_out, int out_size)
{
    const float* x    = (const float*)d_in[0];
    const float* mask = (const float*)d_in[1];
    const float* ln_g = (const float*)d_in[2];
    const float* ln_b = (const float*)d_in[3];
    const float* w1   = (const float*)d_in[4];
    const float* b1   = (const float*)d_in[5];
    const float* w2   = (const float*)d_in[6];
    const float* b2   = (const float*)d_in[7];
    float* out = (float*)d_out;

    float *ft; float2 *tw;
    __half *t, *h, *w1h, *w2h;
    cudaGetSymbolAddress((void**)&ft,  g_ft);
    cudaGetSymbolAddress((void**)&tw,  g_tw);
    cudaGetSymbolAddress((void**)&t,   g_t);
    cudaGetSymbolAddress((void**)&h,   g_h);
    cudaGetSymbolAddress((void**)&w1h, g_w1h);
    cudaGetSymbolAddress((void**)&w2h, g_w2h);

    cudaFuncSetAttribute(fftc_kernel, cudaFuncAttributeMaxDynamicSharedMemorySize, 65536);
    cudaFuncSetAttribute(gemm_mma_kernel, cudaFuncAttributeMaxDynamicSharedMemorySize, GEMM_SMEM);

    twinit_kernel<<<4, 256>>>(tw);
    wsplit_kernel<<<dim3(32, 32), dim3(32, 8)>>>(w1, w1h);
    wsplit_kernel<<<dim3(32, 32), dim3(32, 8)>>>(w2, w2h);
    fftc_kernel<<<dim3(D_ / 8, B_), 512, 65536>>>(x, ft, tw);
    add_ln_kernel<<<ROWS, 256>>>(x, ft, ln_g, ln_b, t);
    gemm_mma_kernel<<<dim3(D_ / 256, ROWS / 128), 512, GEMM_SMEM>>>(
        t, w1h, b1, nullptr, h, nullptr, 0);
    gemm_mma_kernel<<<dim3(D_ / 256, ROWS / 128), 512, GEMM_SMEM>>>(
        h, w2h, b2, mask, nullptr, out, 1);
}

// round 10
// speedup vs baseline: 1.5557x; 1.5557x over previous
#include <cuda_runtime.h>
#include <cuda_bf16.h>
#include <cuda_fp16.h>
#include <math.h>
#include <stdint.h>

// ===========================================================================
// FNet block on GB300 (compute_103 PTX -> mma.sync HMMA path)
//   ft  = Re(FFT_seq(D * reverse_hidden(x)))   [FFT_D^2 = D * index reversal]
//   t   = LayerNorm(x + ft)*g + b   -> fp16
//   h   = GELU(t @ w1 + b1)         -> 1-term fp16 mma GEMM -> fp16
//   out = (h @ w2 + b2) * mask      -> 1-term fp16 mma GEMM -> fp32
// GEMM: 128x128 tile, 4 warps (64x64 warp tile), BK=32, cp.async x2.
// ===========================================================================

#define B_ 8
#define S_ 2048
#define D_ 1024
#define ROWS (B_ * S_)
#define ELEMS ((long)ROWS * D_)

__device__ __align__(256) float   g_ft[ELEMS];
__device__ __align__(256) __half  g_t[ELEMS];
__device__ __align__(256) __half  g_h[ELEMS];
__device__ __align__(256) __half  g_w1h[D_ * D_];
__device__ __align__(256) __half  g_w2h[D_ * D_];
__device__ __align__(256) float2  g_tw[1024];

// ------------------------- helpers ----------------------------------------
__device__ __forceinline__ uint32_t smem_u32(const void* p) {
    uint32_t a;
    asm("{ .reg .u64 t; cvta.to.shared.u64 t, %1; cvt.u32.u64 %0, t; }"
        : "=r"(a) : "l"(p));
    return a;
}
__device__ __forceinline__ void cp16(uint32_t s, const void* g) {
    asm volatile("cp.async.cg.shared.global [%0], [%1], 16;" :: "r"(s), "l"(g));
}
#define CP_COMMIT() asm volatile("cp.async.commit_group;" ::: "memory")
#define CP_WAIT(n)  asm volatile("cp.async.wait_group %0;" :: "n"(n) : "memory")

__device__ __forceinline__ void ldsm_x4(uint32_t* r, uint32_t addr) {
    asm volatile("ldmatrix.sync.aligned.m8n8.x4.shared.b16 {%0,%1,%2,%3}, [%4];"
                 : "=r"(r[0]), "=r"(r[1]), "=r"(r[2]), "=r"(r[3]) : "r"(addr));
}
__device__ __forceinline__ void mma_f16(float* c, const uint32_t* a, const uint32_t* b) {
    asm volatile("mma.sync.aligned.m16n8k16.row.col.f32.f16.f16.f32 "
                 "{%0,%1,%2,%3}, {%4,%5,%6,%7}, {%8,%9}, {%0,%1,%2,%3};"
                 : "+f"(c[0]), "+f"(c[1]), "+f"(c[2]), "+f"(c[3])
                 : "r"(a[0]), "r"(a[1]), "r"(a[2]), "r"(a[3]),
                   "r"(b[0]), "r"(b[1]));
}
__device__ __forceinline__ float2 cmul(float2 a, float2 b) {
    return make_float2(a.x * b.x - a.y * b.y, a.x * b.y + a.y * b.x);
}

// ===========================================================================
// Kernel 0a: twiddle table  tw[t] = exp(-i*pi*t/1024)
// ===========================================================================
__global__ void twinit_kernel(float2* __restrict__ tw) {
    int t = blockIdx.x * 256 + threadIdx.x;
    float s, c;
    sincospif(-(float)t / 1024.0f, &s, &c);
    tw[t] = make_float2(c, s);
}

// ===========================================================================
// Kernel 0b: weight transpose + fp16 convert.  w[K][N] -> wt[N][K] fp16
// ===========================================================================
__global__ __launch_bounds__(256) void wsplit_kernel(
    const float* __restrict__ w, __half* __restrict__ wh)
{
    __shared__ float tile[32][33];
    const int bx = blockIdx.x * 32;
    const int by = blockIdx.y * 32;
    const int tx = threadIdx.x, ty = threadIdx.y;
    for (int i = ty; i < 32; i += 8)
        tile[i][tx] = w[(long)(by + i) * D_ + bx + tx];
    __syncthreads();
    for (int i = ty; i < 32; i += 8) {
        int n = bx + i;
        int k = by + tx;
        wh[(long)n * D_ + k] = __float2half(tile[tx][i]);
    }
}

// ===========================================================================
// Kernel 1: real-packed FFT along seq (8 real cols -> 4 complex FFTs),
// fused radix-4 rounds (h=1,4,16,64,256) + final radix-2 (h=1024).
// Unpack Re, scatter reversed hidden index, scale by D.   [R8-proven]
// ===========================================================================
__global__ __launch_bounds__(512) void fftc_kernel(
    const float* __restrict__ x, float* __restrict__ ft,
    const float2* __restrict__ tw)
{
    extern __shared__ float2 sa[];   // [2048][4] complex = 64 KB
    const int c0  = blockIdx.x * 8;
    const int b   = blockIdx.y;
    const int tid = threadIdx.x;

    const float* xp = x + (long)b * S_ * D_ + c0;
    for (int r = tid; r < S_; r += 512) {
        int br = __brev(r) >> 21;
        float4 v0 = *(const float4*)(xp + (long)r * D_);
        float4 v1 = *(const float4*)(xp + (long)r * D_ + 4);
        float2* d = sa + br * 4;
        d[0] = make_float2(v0.x, v0.y);
        d[1] = make_float2(v0.z, v0.w);
        d[2] = make_float2(v1.x, v1.y);
        d[3] = make_float2(v1.z, v1.w);
    }
    __syncthreads();

    #pragma unroll
    for (int h = 1; h <= 256; h *= 4) {
        const int step1 = 1024 / h;
        const int step2 = 512 / h;
        #pragma unroll
        for (int t = 0; t < 4; t++) {
            int i = tid + t * 512;
            int q = i & 3;
            int g = i >> 2;
            int j = g & (h - 1);
            int i0 = ((g - j) << 2) + j;
            float2 u0 = sa[i0 * 4 + q];
            float2 u1 = sa[(i0 + h) * 4 + q];
            float2 u2 = sa[(i0 + 2 * h) * 4 + q];
            float2 u3 = sa[(i0 + 3 * h) * 4 + q];
            float2 w1 = tw[j * step1];
            float2 wA = tw[j * step2];
            float2 wB = make_float2(wA.y, -wA.x);
            float2 t1 = cmul(w1, u1);
            float2 a0 = make_float2(u0.x + t1.x, u0.y + t1.y);
            float2 a1 = make_float2(u0.x - t1.x, u0.y - t1.y);
            float2 t3 = cmul(w1, u3);
            float2 a2 = make_float2(u2.x + t3.x, u2.y + t3.y);
            float2 a3 = make_float2(u2.x - t3.x, u2.y - t3.y);
            float2 t2 = cmul(wA, a2);
            float2 tB = cmul(wB, a3);
            sa[i0 * 4 + q]           = make_float2(a0.x + t2.x, a0.y + t2.y);
            sa[(i0 + h) * 4 + q]     = make_float2(a1.x + tB.x, a1.y + tB.y);
            sa[(i0 + 2 * h) * 4 + q] = make_float2(a0.x - t2.x, a0.y - t2.y);
            sa[(i0 + 3 * h) * 4 + q] = make_float2(a1.x - tB.x, a1.y - tB.y);
        }
        __syncthreads();
    }

    #pragma unroll
    for (int t = 0; t < 8; t++) {
        int i = tid + t * 512;
        int q = i & 3;
        int p = i >> 2;
        float2 w = tw[p];
        float2 u = sa[p * 4 + q];
        float2 v = sa[(p + 1024) * 4 + q];
        float2 tt = cmul(w, v);
        sa[p * 4 + q]          = make_float2(u.x + tt.x, u.y + tt.y);
        sa[(p + 1024) * 4 + q] = make_float2(u.x - tt.x, u.y - tt.y);
    }
    __syncthreads();

    float* fp = ft + (long)b * S_ * D_;
    for (int i = tid; i < S_ * 8; i += 512) {
        int s   = i >> 3;
        int col = i & 7;
        int q   = col >> 1;
        int ns  = (S_ - s) & (S_ - 1);
        float2 zs = sa[s * 4 + q];
        float2 zn = sa[ns * 4 + q];
        float val = (col & 1) ? (zs.y + zn.y) : (zs.x + zn.x);
        val *= 512.0f;                          // D * 0.5
        int dout = (D_ - (c0 + col)) & (D_ - 1);
        fp[(long)s * D_ + dout] = val;
    }
}

// ===========================================================================
// Kernel 2: t = LN(x + ft)*g + b  -> fp16  (float4 I/O)
// ===========================================================================
__device__ __forceinline__ float block_sum_256(float val, float* sh) {
    #pragma unroll
    for (int o = 16; o > 0; o >>= 1) val += __shfl_xor_sync(0xFFFFFFFFu, val, o);
    int lane = threadIdx.x & 31, w = threadIdx.x >> 5;
    if (lane == 0) sh[w] = val;
    __syncthreads();
    if (w == 0) {
        float v = (lane < 8) ? sh[lane] : 0.0f;
        #pragma unroll
        for (int o = 4; o > 0; o >>= 1) v += __shfl_xor_sync(0xFFFFFFFFu, v, o);
        if (lane == 0) sh[0] = v;
    }
    __syncthreads();
    float r = sh[0];
    __syncthreads();
    return r;
}

__global__ __launch_bounds__(256) void add_ln_kernel(
    const float* __restrict__ x, const float* __restrict__ ft,
    const float* __restrict__ gamma, const float* __restrict__ beta,
    __half* __restrict__ t_out)
{
    __shared__ float sh[8];
    const int row = blockIdx.x;
    const int tid = threadIdx.x;
    const long base = (long)row * D_ + tid * 4;

    float4 xv = *(const float4*)(x + base);
    float4 fv = *(const float4*)(ft + base);
    float v0 = xv.x + fv.x, v1 = xv.y + fv.y, v2 = xv.z + fv.z, v3 = xv.w + fv.w;

    float mu = block_sum_256(v0 + v1 + v2 + v3, sh) * (1.0f / D_);
    float d0 = v0 - mu, d1 = v1 - mu, d2 = v2 - mu, d3 = v3 - mu;
    float var = block_sum_256(d0 * d0 + d1 * d1 + d2 * d2 + d3 * d3, sh) * (1.0f / D_);
    float rs  = rsqrtf(var + 1e-5f);

    float4 gv = *(const float4*)(gamma + tid * 4);
    float4 bv = *(const float4*)(beta + tid * 4);
    float r0 = d0 * rs * gv.x + bv.x;
    float r1 = d1 * rs * gv.y + bv.y;
    float r2 = d2 * rs * gv.z + bv.z;
    float r3 = d3 * rs * gv.w + bv.w;

    __half2 h01 = __floats2half2_rn(r0, r1);
    __half2 h23 = __floats2half2_rn(r2, r3);
    uint2 pk = make_uint2(*(uint32_t*)&h01, *(uint32_t*)&h23);
    *(uint2*)(t_out + base) = pk;
}

// ===========================================================================
// Kernel 3/4: 1-term fp16 GEMM via mma.sync. Tile 128M x 128N x 32K,
// 128 threads (4 warps, 2x2 grid, warp tile 64x64), cp.async double buffer.
// fuse 0: bias+GELU -> fp16.   fuse 1: bias, *mask -> fp32.
// ===========================================================================
#define BK 32
#define ROWB 80                        // 64B data + 16B pad
#define TILE_R_B (128 * ROWB)          // 10240 per 128-row tile
#define OFF_A 0
#define OFF_BW TILE_R_B
#define STAGE_B (2 * TILE_R_B)              // 20480
#define GEMM_SMEM (2 * STAGE_B)             // 40960

__global__ __launch_bounds__(128) void gemm_mma_kernel(
    const __half* __restrict__ A, const __half* __restrict__ Bw,
    const float* __restrict__ bias, const float* __restrict__ mask,
    __half* __restrict__ Ch, float* __restrict__ Cf, int fuse)
{
    extern __shared__ char sm[];
    const uint32_t sb  = smem_u32(sm);
    const int tid  = threadIdx.x;
    const int wid  = tid >> 5;
    const int lane = tid & 31;
    const int bm = blockIdx.y * 128;
    const int bn = blockIdx.x * 128;
    const int warp_m = wid & 1;        // 64-row slab
    const int warp_n = wid >> 1;       // 64-col slab

    auto load_stage = [&](int stage, int k0) {
        const uint32_t st = sb + stage * STAGE_B;
        #pragma unroll
        for (int t = 0; t < 4; t++) {   // A: 512 chunks, 4 per thread
            int idx = tid + t * 128;
            int row = idx >> 2, ch = idx & 3;
            uint32_t so = row * ROWB + ch * 16;
            long ga = (long)(bm + row) * D_ + k0 + ch * 8;
            cp16(st + OFF_A + so, A + ga);
        }
        #pragma unroll
        for (int t = 0; t < 4; t++) {   // W: 512 chunks, 4 per thread
            int idx = tid + t * 128;
            int row = idx >> 2, ch = idx & 3;
            uint32_t so = row * ROWB + ch * 16;
            long gb = (long)(bn + row) * D_ + k0 + ch * 8;
            cp16(st + OFF_BW + so, Bw + gb);
        }
    };

    float acc[4][8][4];
    #pragma unroll
    for (int m = 0; m < 4; m++)
        #pragma unroll
        for (int n = 0; n < 8; n++)
            #pragma unroll
            for (int q = 0; q < 4; q++) acc[m][n][q] = 0.0f;

    load_stage(0, 0);
    CP_COMMIT();

    const int a_lrow = lane & 15;
    const int a_kch  = lane >> 4;
    const int b_lrow = ((lane >> 4) & 1) * 8 + (lane & 7);
    const int b_kch  = (lane >> 3) & 1;

    const int NIT = D_ / BK;   // 32
    for (int it = 0; it < NIT; it++) {
        const int s = it & 1;
        if (it + 1 < NIT) {
            load_stage(s ^ 1, (it + 1) * BK);
            CP_COMMIT();
            CP_WAIT(1);
        } else {
            CP_WAIT(0);
        }
        __syncthreads();

        const uint32_t tA  = sb + s * STAGE_B + OFF_A;
        const uint32_t tBw = sb + s * STAGE_B + OFF_BW;

        #pragma unroll
        for (int ks = 0; ks < 2; ks++) {
            const int kb = ks * 32;
            uint32_t ah[4][4];
            #pragma unroll
            for (int m = 0; m < 4; m++) {
                uint32_t off = (uint32_t)((warp_m * 64 + m * 16 + a_lrow) * ROWB
                                          + kb + a_kch * 16);
                ldsm_x4(ah[m], tA + off);
            }
            #pragma unroll
            for (int p = 0; p < 4; p++) {
                uint32_t off = (uint32_t)((warp_n * 64 + p * 16 + b_lrow) * ROWB
                                          + kb + b_kch * 16);
                uint32_t rh[4];
                ldsm_x4(rh, tBw + off);
                #pragma unroll
                for (int m = 0; m < 4; m++) {
                    mma_f16(acc[m][2 * p],     ah[m], rh);
                    mma_f16(acc[m][2 * p + 1], ah[m], rh + 2);
                }
            }
        }
        __syncthreads();
    }

    // ------------------------------ epilogue -------------------------------
    const int g  = lane >> 2;
    const int t2 = (lane & 3) * 2;
    #pragma unroll
    for (int m = 0; m < 4; m++) {
        const int row0 = bm + warp_m * 64 + m * 16 + g;
        #pragma unroll
        for (int half = 0; half < 2; half++) {
            const int row = row0 + half * 8;
            const float mk = (fuse == 1) ? mask[row] : 0.0f;
            #pragma unroll
            for (int n = 0; n < 8; n++) {
                const int col = bn + warp_n * 64 + n * 8 + t2;
                float v0 = acc[m][n][2 * half]     + bias[col];
                float v1 = acc[m][n][2 * half + 1] + bias[col + 1];
                if (fuse == 0) {
                    v0 = 0.5f * v0 * (1.0f + erff(v0 * 0.70710678118654752f));
                    v1 = 0.5f * v1 * (1.0f + erff(v1 * 0.70710678118654752f));
                    __half h0 = __float2half(v0);
                    __half h1 = __float2half(v1);
                    uint32_t hp = ((uint32_t)__half_as_ushort(h1) << 16)
                                | __half_as_ushort(h0);
                    *(uint32_t*)(Ch + (long)row * D_ + col) = hp;
                } else {
                    float2 o = make_float2(v0 * mk, v1 * mk);
                    *(float2*)(Cf + (long)row * D_ + col) = o;
                }
            }
        }
    }
}

// ===========================================================================
// Launch
// ===========================================================================
extern "C" void kernel_launch(void* const* d_in, const int* in_sizes, int n_in,
                              void* d_out, int out_size)
{
    const float* x    = (const float*)d_in[0];
    const float* mask = (const float*)d_in[1];
    const float* ln_g = (const float*)d_in[2];
    const float* ln_b = (const float*)d_in[3];
    const float* w1   = (const float*)d_in[4];
    const float* b1   = (const float*)d_in[5];
    const float* w2   = (const float*)d_in[6];
    const float* b2   = (const float*)d_in[7];
    float* out = (float*)d_out;

    float *ft; float2 *tw;
    __half *t, *h, *w1h, *w2h;
    cudaGetSymbolAddress((void**)&ft,  g_ft);
    cudaGetSymbolAddress((void**)&tw,  g_tw);
    cudaGetSymbolAddress((void**)&t,   g_t);
    cudaGetSymbolAddress((void**)&h,   g_h);
    cudaGetSymbolAddress((void**)&w1h, g_w1h);
    cudaGetSymbolAddress((void**)&w2h, g_w2h);

    cudaFuncSetAttribute(fftc_kernel, cudaFuncAttributeMaxDynamicSharedMemorySize, 65536);
    cudaFuncSetAttribute(gemm_mma_kernel, cudaFuncAttributeMaxDynamicSharedMemorySize, GEMM_SMEM);

    twinit_kernel<<<4, 256>>>(tw);
    wsplit_kernel<<<dim3(32, 32), dim3(32, 8)>>>(w1, w1h);
    wsplit_kernel<<<dim3(32, 32), dim3(32, 8)>>>(w2, w2h);
    fftc_kernel<<<dim3(D_ / 8, B_), 512, 65536>>>(x, ft, tw);
    add_ln_kernel<<<ROWS, 256>>>(x, ft, ln_g, ln_b, t);
    gemm_mma_kernel<<<dim3(D_ / 128, ROWS / 128), 128, GEMM_SMEM>>>(
        t, w1h, b1, nullptr, h, nullptr, 0);
    gemm_mma_kernel<<<dim3(D_ / 128, ROWS / 128), 128, GEMM_SMEM>>>(
        h, w2h, b2, mask, nullptr, out, 1);
}

// round 11
// speedup vs baseline: 1.5649x; 1.0059x over previous
#include <cuda_runtime.h>
#include <cuda_bf16.h>
#include <cuda_fp16.h>
#include <math.h>
#include <stdint.h>

// ===========================================================================
// FNet block on GB300 (compute_103 PTX -> mma.sync HMMA path)
//   ft  = Re(FFT_seq(D * reverse_hidden(x)))   [FFT_D^2 = D * index reversal]
//   t   = LayerNorm(x + ft)*g + b   -> fp16
//   h   = GELU(t @ w1 + b1)         -> 1-term fp16 mma GEMM -> fp16
//   out = (h @ w2 + b2) * mask      -> 1-term fp16 mma GEMM -> fp32
// FFT smem uses padded index map f(e,q)=4e+q+2(e>>2)+2(e>>6) to kill the
// 8-way (butterfly) and 32-way (bit-reversed store) bank conflicts.
// ===========================================================================

#define B_ 8
#define S_ 2048
#define D_ 1024
#define ROWS (B_ * S_)
#define ELEMS ((long)ROWS * D_)

__device__ __align__(256) float   g_ft[ELEMS];
__device__ __align__(256) __half  g_t[ELEMS];
__device__ __align__(256) __half  g_h[ELEMS];
__device__ __align__(256) __half  g_w1h[D_ * D_];
__device__ __align__(256) __half  g_w2h[D_ * D_];
__device__ __align__(256) float2  g_tw[1024];

// ------------------------- helpers ----------------------------------------
__device__ __forceinline__ uint32_t smem_u32(const void* p) {
    uint32_t a;
    asm("{ .reg .u64 t; cvta.to.shared.u64 t, %1; cvt.u32.u64 %0, t; }"
        : "=r"(a) : "l"(p));
    return a;
}
__device__ __forceinline__ void cp16(uint32_t s, const void* g) {
    asm volatile("cp.async.cg.shared.global [%0], [%1], 16;" :: "r"(s), "l"(g));
}
#define CP_COMMIT() asm volatile("cp.async.commit_group;" ::: "memory")
#define CP_WAIT(n)  asm volatile("cp.async.wait_group %0;" :: "n"(n) : "memory")

__device__ __forceinline__ void ldsm_x4(uint32_t* r, uint32_t addr) {
    asm volatile("ldmatrix.sync.aligned.m8n8.x4.shared.b16 {%0,%1,%2,%3}, [%4];"
                 : "=r"(r[0]), "=r"(r[1]), "=r"(r[2]), "=r"(r[3]) : "r"(addr));
}
__device__ __forceinline__ void mma_f16(float* c, const uint32_t* a, const uint32_t* b) {
    asm volatile("mma.sync.aligned.m16n8k16.row.col.f32.f16.f16.f32 "
                 "{%0,%1,%2,%3}, {%4,%5,%6,%7}, {%8,%9}, {%0,%1,%2,%3};"
                 : "+f"(c[0]), "+f"(c[1]), "+f"(c[2]), "+f"(c[3])
                 : "r"(a[0]), "r"(a[1]), "r"(a[2]), "r"(a[3]),
                   "r"(b[0]), "r"(b[1]));
}
__device__ __forceinline__ float2 cmul(float2 a, float2 b) {
    return make_float2(a.x * b.x - a.y * b.y, a.x * b.y + a.y * b.x);
}

// padded smem index for the FFT working set (in float2 units)
__device__ __forceinline__ int sidx(int e, int q) {
    return e * 4 + q + 2 * (e >> 2) + 2 * (e >> 6);
}
#define FFT_SMEM_F2 9276
#define FFT_SMEM_BYTES (FFT_SMEM_F2 * 8)   // 74208

// ===========================================================================
// Kernel 0a: twiddle table  tw[t] = exp(-i*pi*t/1024)
// ===========================================================================
__global__ void twinit_kernel(float2* __restrict__ tw) {
    int t = blockIdx.x * 256 + threadIdx.x;
    float s, c;
    sincospif(-(float)t / 1024.0f, &s, &c);
    tw[t] = make_float2(c, s);
}

// ===========================================================================
// Kernel 0b: weight transpose + fp16 convert.  w[K][N] -> wt[N][K] fp16
// ===========================================================================
__global__ __launch_bounds__(256) void wsplit_kernel(
    const float* __restrict__ w, __half* __restrict__ wh)
{
    __shared__ float tile[32][33];
    const int bx = blockIdx.x * 32;
    const int by = blockIdx.y * 32;
    const int tx = threadIdx.x, ty = threadIdx.y;
    for (int i = ty; i < 32; i += 8)
        tile[i][tx] = w[(long)(by + i) * D_ + bx + tx];
    __syncthreads();
    for (int i = ty; i < 32; i += 8) {
        int n = bx + i;
        int k = by + tx;
        wh[(long)n * D_ + k] = __float2half(tile[tx][i]);
    }
}

// ===========================================================================
// Kernel 1: real-packed FFT along seq (8 real cols -> 4 complex FFTs),
// fused radix-4 rounds (h=1,4,16,64,256) + final radix-2 (h=1024).
// Padded smem indexing (sidx) for conflict-free butterflies.
// ===========================================================================
__global__ __launch_bounds__(512) void fftc_kernel(
    const float* __restrict__ x, float* __restrict__ ft,
    const float2* __restrict__ tw)
{
    extern __shared__ float2 sa[];   // FFT_SMEM_F2 float2
    const int c0  = blockIdx.x * 8;
    const int b   = blockIdx.y;
    const int tid = threadIdx.x;

    const float* xp = x + (long)b * S_ * D_ + c0;
    for (int r = tid; r < S_; r += 512) {
        int br = __brev(r) >> 21;
        float4 v0 = *(const float4*)(xp + (long)r * D_);
        float4 v1 = *(const float4*)(xp + (long)r * D_ + 4);
        float2* d = sa + sidx(br, 0);     // q=0..3 contiguous
        d[0] = make_float2(v0.x, v0.y);
        d[1] = make_float2(v0.z, v0.w);
        d[2] = make_float2(v1.x, v1.y);
        d[3] = make_float2(v1.z, v1.w);
    }
    __syncthreads();

    #pragma unroll
    for (int h = 1; h <= 256; h *= 4) {
        const int step1 = 1024 / h;
        const int step2 = 512 / h;
        #pragma unroll
        for (int t = 0; t < 4; t++) {
            int i = tid + t * 512;
            int q = i & 3;
            int g = i >> 2;
            int j = g & (h - 1);
            int i0 = ((g - j) << 2) + j;
            float2 u0 = sa[sidx(i0, q)];
            float2 u1 = sa[sidx(i0 + h, q)];
            float2 u2 = sa[sidx(i0 + 2 * h, q)];
            float2 u3 = sa[sidx(i0 + 3 * h, q)];
            float2 w1 = tw[j * step1];
            float2 wA = tw[j * step2];
            float2 wB = make_float2(wA.y, -wA.x);
            float2 t1 = cmul(w1, u1);
            float2 a0 = make_float2(u0.x + t1.x, u0.y + t1.y);
            float2 a1 = make_float2(u0.x - t1.x, u0.y - t1.y);
            float2 t3 = cmul(w1, u3);
            float2 a2 = make_float2(u2.x + t3.x, u2.y + t3.y);
            float2 a3 = make_float2(u2.x - t3.x, u2.y - t3.y);
            float2 t2 = cmul(wA, a2);
            float2 tB = cmul(wB, a3);
            sa[sidx(i0, q)]         = make_float2(a0.x + t2.x, a0.y + t2.y);
            sa[sidx(i0 + h, q)]     = make_float2(a1.x + tB.x, a1.y + tB.y);
            sa[sidx(i0 + 2 * h, q)] = make_float2(a0.x - t2.x, a0.y - t2.y);
            sa[sidx(i0 + 3 * h, q)] = make_float2(a1.x - tB.x, a1.y - tB.y);
        }
        __syncthreads();
    }

    #pragma unroll
    for (int t = 0; t < 8; t++) {
        int i = tid + t * 512;
        int q = i & 3;
        int p = i >> 2;
        float2 w = tw[p];
        float2 u = sa[sidx(p, q)];
        float2 v = sa[sidx(p + 1024, q)];
        float2 tt = cmul(w, v);
        sa[sidx(p, q)]        = make_float2(u.x + tt.x, u.y + tt.y);
        sa[sidx(p + 1024, q)] = make_float2(u.x - tt.x, u.y - tt.y);
    }
    __syncthreads();

    float* fp = ft + (long)b * S_ * D_;
    for (int i = tid; i < S_ * 8; i += 512) {
        int s   = i >> 3;
        int col = i & 7;
        int q   = col >> 1;
        int ns  = (S_ - s) & (S_ - 1);
        float2 zs = sa[sidx(s, q)];
        float2 zn = sa[sidx(ns, q)];
        float val = (col & 1) ? (zs.y + zn.y) : (zs.x + zn.x);
        val *= 512.0f;                          // D * 0.5
        int dout = (D_ - (c0 + col)) & (D_ - 1);
        fp[(long)s * D_ + dout] = val;
    }
}

// ===========================================================================
// Kernel 2: t = LN(x + ft)*g + b  -> fp16  (float4 I/O)
// ===========================================================================
__device__ __forceinline__ float block_sum_256(float val, float* sh) {
    #pragma unroll
    for (int o = 16; o > 0; o >>= 1) val += __shfl_xor_sync(0xFFFFFFFFu, val, o);
    int lane = threadIdx.x & 31, w = threadIdx.x >> 5;
    if (lane == 0) sh[w] = val;
    __syncthreads();
    if (w == 0) {
        float v = (lane < 8) ? sh[lane] : 0.0f;
        #pragma unroll
        for (int o = 4; o > 0; o >>= 1) v += __shfl_xor_sync(0xFFFFFFFFu, v, o);
        if (lane == 0) sh[0] = v;
    }
    __syncthreads();
    float r = sh[0];
    __syncthreads();
    return r;
}

__global__ __launch_bounds__(256) void add_ln_kernel(
    const float* __restrict__ x, const float* __restrict__ ft,
    const float* __restrict__ gamma, const float* __restrict__ beta,
    __half* __restrict__ t_out)
{
    __shared__ float sh[8];
    const int row = blockIdx.x;
    const int tid = threadIdx.x;
    const long base = (long)row * D_ + tid * 4;

    float4 xv = *(const float4*)(x + base);
    float4 fv = *(const float4*)(ft + base);
    float v0 = xv.x + fv.x, v1 = xv.y + fv.y, v2 = xv.z + fv.z, v3 = xv.w + fv.w;

    float mu = block_sum_256(v0 + v1 + v2 + v3, sh) * (1.0f / D_);
    float d0 = v0 - mu, d1 = v1 - mu, d2 = v2 - mu, d3 = v3 - mu;
    float var = block_sum_256(d0 * d0 + d1 * d1 + d2 * d2 + d3 * d3, sh) * (1.0f / D_);
    float rs  = rsqrtf(var + 1e-5f);

    float4 gv = *(const float4*)(gamma + tid * 4);
    float4 bv = *(const float4*)(beta + tid * 4);
    float r0 = d0 * rs * gv.x + bv.x;
    float r1 = d1 * rs * gv.y + bv.y;
    float r2 = d2 * rs * gv.z + bv.z;
    float r3 = d3 * rs * gv.w + bv.w;

    __half2 h01 = __floats2half2_rn(r0, r1);
    __half2 h23 = __floats2half2_rn(r2, r3);
    uint2 pk = make_uint2(*(uint32_t*)&h01, *(uint32_t*)&h23);
    *(uint2*)(t_out + base) = pk;
}

// ===========================================================================
// Kernel 3/4: 1-term fp16 GEMM via mma.sync. Tile 128M x 128N x 32K,
// 128 threads (4 warps, 2x2 grid, warp tile 64x64), cp.async double buffer.
// fuse 0: bias+GELU -> fp16.   fuse 1: bias, *mask -> fp32.   [R10-proven]
// ===========================================================================
#define BK 32
#define ROWB 80                        // 64B data + 16B pad
#define TILE_R_B (128 * ROWB)          // 10240 per 128-row tile
#define OFF_A 0
#define OFF_BW TILE_R_B
#define STAGE_B (2 * TILE_R_B)              // 20480
#define GEMM_SMEM (2 * STAGE_B)             // 40960

__global__ __launch_bounds__(128) void gemm_mma_kernel(
    const __half* __restrict__ A, const __half* __restrict__ Bw,
    const float* __restrict__ bias, const float* __restrict__ mask,
    __half* __restrict__ Ch, float* __restrict__ Cf, int fuse)
{
    extern __shared__ char sm[];
    const uint32_t sb  = smem_u32(sm);
    const int tid  = threadIdx.x;
    const int wid  = tid >> 5;
    const int lane = tid & 31;
    const int bm = blockIdx.y * 128;
    const int bn = blockIdx.x * 128;
    const int warp_m = wid & 1;        // 64-row slab
    const int warp_n = wid >> 1;       // 64-col slab

    auto load_stage = [&](int stage, int k0) {
        const uint32_t st = sb + stage * STAGE_B;
        #pragma unroll
        for (int t = 0; t < 4; t++) {   // A: 512 chunks, 4 per thread
            int idx = tid + t * 128;
            int row = idx >> 2, ch = idx & 3;
            uint32_t so = row * ROWB + ch * 16;
            long ga = (long)(bm + row) * D_ + k0 + ch * 8;
            cp16(st + OFF_A + so, A + ga);
        }
        #pragma unroll
        for (int t = 0; t < 4; t++) {   // W: 512 chunks, 4 per thread
            int idx = tid + t * 128;
            int row = idx >> 2, ch = idx & 3;
            uint32_t so = row * ROWB + ch * 16;
            long gb = (long)(bn + row) * D_ + k0 + ch * 8;
            cp16(st + OFF_BW + so, Bw + gb);
        }
    };

    float acc[4][8][4];
    #pragma unroll
    for (int m = 0; m < 4; m++)
        #pragma unroll
        for (int n = 0; n < 8; n++)
            #pragma unroll
            for (int q = 0; q < 4; q++) acc[m][n][q] = 0.0f;

    load_stage(0, 0);
    CP_COMMIT();

    const int a_lrow = lane & 15;
    const int a_kch  = lane >> 4;
    const int b_lrow = ((lane >> 4) & 1) * 8 + (lane & 7);
    const int b_kch  = (lane >> 3) & 1;

    const int NIT = D_ / BK;   // 32
    for (int it = 0; it < NIT; it++) {
        const int s = it & 1;
        if (it + 1 < NIT) {
            load_stage(s ^ 1, (it + 1) * BK);
            CP_COMMIT();
            CP_WAIT(1);
        } else {
            CP_WAIT(0);
        }
        __syncthreads();

        const uint32_t tA  = sb + s * STAGE_B + OFF_A;
        const uint32_t tBw = sb + s * STAGE_B + OFF_BW;

        #pragma unroll
        for (int ks = 0; ks < 2; ks++) {
            const int kb = ks * 32;
            uint32_t ah[4][4];
            #pragma unroll
            for (int m = 0; m < 4; m++) {
                uint32_t off = (uint32_t)((warp_m * 64 + m * 16 + a_lrow) * ROWB
                                          + kb + a_kch * 16);
                ldsm_x4(ah[m], tA + off);
            }
            #pragma unroll
            for (int p = 0; p < 4; p++) {
                uint32_t off = (uint32_t)((warp_n * 64 + p * 16 + b_lrow) * ROWB
                                          + kb + b_kch * 16);
                uint32_t rh[4];
                ldsm_x4(rh, tBw + off);
                #pragma unroll
                for (int m = 0; m < 4; m++) {
                    mma_f16(acc[m][2 * p],     ah[m], rh);
                    mma_f16(acc[m][2 * p + 1], ah[m], rh + 2);
                }
            }
        }
        __syncthreads();
    }

    // ------------------------------ epilogue -------------------------------
    const int g  = lane >> 2;
    const int t2 = (lane & 3) * 2;
    #pragma unroll
    for (int m = 0; m < 4; m++) {
        const int row0 = bm + warp_m * 64 + m * 16 + g;
        #pragma unroll
        for (int half = 0; half < 2; half++) {
            const int row = row0 + half * 8;
            const float mk = (fuse == 1) ? mask[row] : 0.0f;
            #pragma unroll
            for (int n = 0; n < 8; n++) {
                const int col = bn + warp_n * 64 + n * 8 + t2;
                float v0 = acc[m][n][2 * half]     + bias[col];
                float v1 = acc[m][n][2 * half + 1] + bias[col + 1];
                if (fuse == 0) {
                    v0 = 0.5f * v0 * (1.0f + erff(v0 * 0.70710678118654752f));
                    v1 = 0.5f * v1 * (1.0f + erff(v1 * 0.70710678118654752f));
                    __half h0 = __float2half(v0);
                    __half h1 = __float2half(v1);
                    uint32_t hp = ((uint32_t)__half_as_ushort(h1) << 16)
                                | __half_as_ushort(h0);
                    *(uint32_t*)(Ch + (long)row * D_ + col) = hp;
                } else {
                    float2 o = make_float2(v0 * mk, v1 * mk);
                    *(float2*)(Cf + (long)row * D_ + col) = o;
                }
            }
        }
    }
}

// ===========================================================================
// Launch
// ===========================================================================
extern "C" void kernel_launch(void* const* d_in, const int* in_sizes, int n_in,
                              void* d_out, int out_size)
{
    const float* x    = (const float*)d_in[0];
    const float* mask = (const float*)d_in[1];
    const float* ln_g = (const float*)d_in[2];
    const float* ln_b = (const float*)d_in[3];
    const float* w1   = (const float*)d_in[4];
    const float* b1   = (const float*)d_in[5];
    const float* w2   = (const float*)d_in[6];
    const float* b2   = (const float*)d_in[7];
    float* out = (float*)d_out;

    float *ft; float2 *tw;
    __half *t, *h, *w1h, *w2h;
    cudaGetSymbolAddress((void**)&ft,  g_ft);
    cudaGetSymbolAddress((void**)&tw,  g_tw);
    cudaGetSymbolAddress((void**)&t,   g_t);
    cudaGetSymbolAddress((void**)&h,   g_h);
    cudaGetSymbolAddress((void**)&w1h, g_w1h);
    cudaGetSymbolAddress((void**)&w2h, g_w2h);

    cudaFuncSetAttribute(fftc_kernel, cudaFuncAttributeMaxDynamicSharedMemorySize, FFT_SMEM_BYTES);
    cudaFuncSetAttribute(gemm_mma_kernel, cudaFuncAttributeMaxDynamicSharedMemorySize, GEMM_SMEM);

    twinit_kernel<<<4, 256>>>(tw);
    wsplit_kernel<<<dim3(32, 32), dim3(32, 8)>>>(w1, w1h);
    wsplit_kernel<<<dim3(32, 32), dim3(32, 8)>>>(w2, w2h);
    fftc_kernel<<<dim3(D_ / 8, B_), 512, FFT_SMEM_BYTES>>>(x, ft, tw);
    add_ln_kernel<<<ROWS, 256>>>(x, ft, ln_g, ln_b, t);
    gemm_mma_kernel<<<dim3(D_ / 128, ROWS / 128), 128, GEMM_SMEM>>>(
        t, w1h, b1, nullptr, h, nullptr, 0);
    gemm_mma_kernel<<<dim3(D_ / 128, ROWS / 128), 128, GEMM_SMEM>>>(
        h, w2h, b2, mask, nullptr, out, 1);
}